// round 1
// baseline (speedup 1.0000x reference)
#include <cuda_runtime.h>
#include <math.h>

#define FDIM 256
#define BMAX 1024
#define MMAX 500000

// Scratch (allocation-free: __device__ globals)
__device__ float    g_groot[BMAX * FDIM];   // per-root x_r * w_ego_root * w_ego_u
__device__ float    g_nr[BMAX];             // ||x_r * w_ego_root||
__device__ float    g_sv[BMAX];             // x_r . w_layer_v
__device__ float    g_bf[BMAX];             // budgets / 200
__device__ unsigned g_pnorm[BMAX];          // encoded float max
__device__ float    g_agg[MMAX];            // segment_sum(sv[edge_src] -> edge_dst)
__device__ float    g_pu[MMAX];             // p_u before normalization

__device__ __forceinline__ unsigned f2key(float f) {
    unsigned u = __float_as_uint(f);
    return (u & 0x80000000u) ? ~u : (u | 0x80000000u);
}
__device__ __forceinline__ float key2f(unsigned k) {
    unsigned u = (k & 0x80000000u) ? (k ^ 0x80000000u) : ~k;
    return __uint_as_float(u);
}

// K1: per-root precompute. One block (256 threads) per root.
__global__ void k_root(const float* __restrict__ x,
                       const float* __restrict__ w_ego_root,
                       const float* __restrict__ w_ego_u,
                       const float* __restrict__ w_layer_v,
                       const float* __restrict__ budgets,
                       const int*   __restrict__ batch_nodes)
{
    int b = blockIdx.x;
    int f = threadIdx.x;
    float xr = x[(size_t)batch_nodes[b] * FDIM + f];
    float h  = xr * w_ego_root[f];
    g_groot[b * FDIM + f] = h * w_ego_u[f];
    float s1 = h * h;               // for nr^2
    float s2 = xr * w_layer_v[f];   // for sv

    __shared__ float sh1[8], sh2[8];
    #pragma unroll
    for (int o = 16; o; o >>= 1) {
        s1 += __shfl_xor_sync(0xffffffffu, s1, o);
        s2 += __shfl_xor_sync(0xffffffffu, s2, o);
    }
    int w = f >> 5, l = f & 31;
    if (l == 0) { sh1[w] = s1; sh2[w] = s2; }
    __syncthreads();
    if (f == 0) {
        float t1 = 0.f, t2 = 0.f;
        #pragma unroll
        for (int i = 0; i < 8; i++) { t1 += sh1[i]; t2 += sh2[i]; }
        g_nr[b] = sqrtf(t1);
        g_sv[b] = t2;
        g_bf[b] = budgets[b] * (1.0f / 200.0f);
        g_pnorm[b] = f2key(-INFINITY);
    }
}

// K2: zero agg
__global__ void k_zero(int M)
{
    int i = blockIdx.x * blockDim.x + threadIdx.x;
    if (i < M) g_agg[i] = 0.0f;
}

// K3: edge scatter-add
__global__ void k_edge(const int* __restrict__ edge_src,
                       const int* __restrict__ edge_dst, int E)
{
    int i = blockIdx.x * blockDim.x + threadIdx.x;
    if (i < E) atomicAdd(&g_agg[edge_dst[i]], g_sv[edge_src[i]]);
}

// K4: per-candidate scores. One warp per candidate; 8 candidates per 256-thread block.
__global__ void k_cand(const float* __restrict__ x,
                       const float* __restrict__ w_ego_u,
                       const float* __restrict__ w_layer_u,
                       const float* __restrict__ n_imp,
                       const int*   __restrict__ u_ids,
                       const int*   __restrict__ batch_ptr, int M)
{
    __shared__ __align__(16) float s_weu[FDIM];
    __shared__ __align__(16) float s_wlu[FDIM];
    int t = threadIdx.x;
    s_weu[t] = w_ego_u[t];
    s_wlu[t] = w_layer_u[t];
    __syncthreads();

    int warp = t >> 5, lane = t & 31;
    int m = blockIdx.x * 8 + warp;
    if (m >= M) return;

    int u = u_ids[m];
    int b = batch_ptr[m];
    const float4* xu = (const float4*)(x + (size_t)u * FDIM);
    const float4* gr = (const float4*)(g_groot + (size_t)b * FDIM);
    const float4* we = (const float4*)s_weu;
    const float4* wl = (const float4*)s_wlu;

    float dot = 0.f, nu2 = 0.f, su = 0.f;
    #pragma unroll
    for (int c = 0; c < 2; c++) {
        int idx = lane + c * 32;       // float4 index 0..63 -> 256 floats
        float4 xv = xu[idx];
        float4 gv = gr[idx];
        float4 ev = we[idx];
        float4 lv = wl[idx];
        dot += xv.x * gv.x + xv.y * gv.y + xv.z * gv.z + xv.w * gv.w;
        float a0 = xv.x * ev.x, a1 = xv.y * ev.y, a2 = xv.z * ev.z, a3 = xv.w * ev.w;
        nu2 += a0 * a0 + a1 * a1 + a2 * a2 + a3 * a3;
        su  += xv.x * lv.x + xv.y * lv.y + xv.z * lv.z + xv.w * lv.w;
    }
    #pragma unroll
    for (int o = 16; o; o >>= 1) {
        dot += __shfl_xor_sync(0xffffffffu, dot, o);
        nu2 += __shfl_xor_sync(0xffffffffu, nu2, o);
        su  += __shfl_xor_sync(0xffffffffu, su,  o);
    }
    if (lane == 0) {
        float nu    = sqrtf(nu2);
        float ego   = dot / (fmaxf(g_nr[b], 1e-6f) * fmaxf(nu, 1e-6f));
        float layer = tanhf(g_agg[m] + su);
        float p = (0.5f * ego + 0.5f * layer) * n_imp[u] * g_bf[b];
        g_pu[m] = p;
        atomicMax(&g_pnorm[b], f2key(p));
    }
}

// K5: normalize + nan/inf replace + clip
__global__ void k_final(const int* __restrict__ batch_ptr,
                        float* __restrict__ out, int M)
{
    int m = blockIdx.x * blockDim.x + threadIdx.x;
    if (m >= M) return;
    float pn = key2f(g_pnorm[batch_ptr[m]]);
    float p = g_pu[m] / pn + 1.0f;
    if (isnan(p)) p = 0.0f;
    else if (isinf(p)) p = 1.0f;
    p = fminf(fmaxf(p, 1e-5f), 1.0f);
    out[m] = p;
}

extern "C" void kernel_launch(void* const* d_in, const int* in_sizes, int n_in,
                              void* d_out, int out_size)
{
    const float* x           = (const float*)d_in[0];
    const float* w_ego_root  = (const float*)d_in[1];
    const float* w_ego_u     = (const float*)d_in[2];
    const float* w_layer_v   = (const float*)d_in[3];
    const float* w_layer_u   = (const float*)d_in[4];
    const float* n_imp       = (const float*)d_in[5];
    const float* budgets     = (const float*)d_in[6];
    const int*   batch_nodes = (const int*)d_in[7];
    const int*   u_ids       = (const int*)d_in[8];
    const int*   batch_ptr   = (const int*)d_in[9];
    const int*   edge_src    = (const int*)d_in[10];
    const int*   edge_dst    = (const int*)d_in[11];
    float* out = (float*)d_out;

    int B = in_sizes[7];
    int M = in_sizes[8];
    int E = in_sizes[10];

    k_root<<<B, FDIM>>>(x, w_ego_root, w_ego_u, w_layer_v, budgets, batch_nodes);
    k_zero<<<(M + 255) / 256, 256>>>(M);
    k_edge<<<(E + 255) / 256, 256>>>(edge_src, edge_dst, E);
    k_cand<<<(M + 7) / 8, 256>>>(x, w_ego_u, w_layer_u, n_imp, u_ids, batch_ptr, M);
    k_final<<<(M + 255) / 256, 256>>>(batch_ptr, out, M);
}

// round 2
// speedup vs baseline: 1.6393x; 1.6393x over previous
#include <cuda_runtime.h>
#include <math.h>

#define FDIM 256
#define BMAX 1024
#define MMAX 500000

// Scratch (allocation-free: __device__ globals)
__device__ float    g_groot[BMAX * FDIM];   // per-root x_r * w_ego_root * w_ego_u
__device__ float    g_nr[BMAX];             // ||x_r * w_ego_root||
__device__ float    g_sv[BMAX];             // x_r . w_layer_v
__device__ float    g_bf[BMAX];             // budgets / 200
__device__ unsigned g_pnorm[BMAX];          // encoded float max
__device__ float    g_agg[MMAX];            // segment_sum(sv[edge_src] -> edge_dst)
__device__ float    g_pu[MMAX];             // p_u before normalization

__device__ __forceinline__ unsigned f2key(float f) {
    unsigned u = __float_as_uint(f);
    return (u & 0x80000000u) ? ~u : (u | 0x80000000u);
}
__device__ __forceinline__ float key2f(unsigned k) {
    unsigned u = (k & 0x80000000u) ? (k ^ 0x80000000u) : ~k;
    return __uint_as_float(u);
}

__device__ __forceinline__ float dot4(float4 a, float4 b) {
    return a.x * b.x + a.y * b.y + a.z * b.z + a.w * b.w;
}

// K1: per-root precompute. One block (256 threads) per root.
__global__ void k_root(const float* __restrict__ x,
                       const float* __restrict__ w_ego_root,
                       const float* __restrict__ w_ego_u,
                       const float* __restrict__ w_layer_v,
                       const float* __restrict__ budgets,
                       const int*   __restrict__ batch_nodes)
{
    int b = blockIdx.x;
    int f = threadIdx.x;
    float xr = x[(size_t)batch_nodes[b] * FDIM + f];
    float h  = xr * w_ego_root[f];
    g_groot[b * FDIM + f] = h * w_ego_u[f];
    float s1 = h * h;               // for nr^2
    float s2 = xr * w_layer_v[f];   // for sv

    __shared__ float sh1[8], sh2[8];
    #pragma unroll
    for (int o = 16; o; o >>= 1) {
        s1 += __shfl_xor_sync(0xffffffffu, s1, o);
        s2 += __shfl_xor_sync(0xffffffffu, s2, o);
    }
    int w = f >> 5, l = f & 31;
    if (l == 0) { sh1[w] = s1; sh2[w] = s2; }
    __syncthreads();
    if (f == 0) {
        float t1 = 0.f, t2 = 0.f;
        #pragma unroll
        for (int i = 0; i < 8; i++) { t1 += sh1[i]; t2 += sh2[i]; }
        g_nr[b] = sqrtf(t1);
        g_sv[b] = t2;
        g_bf[b] = budgets[b] * (1.0f / 200.0f);
        g_pnorm[b] = f2key(-INFINITY);
    }
}

// K2: zero agg (vectorized)
__global__ void k_zero(int M)
{
    int i = blockIdx.x * blockDim.x + threadIdx.x;
    int i4 = i * 4;
    if (i4 + 3 < M) {
        *(float4*)(g_agg + i4) = make_float4(0.f, 0.f, 0.f, 0.f);
    } else {
        for (int j = i4; j < M; j++) g_agg[j] = 0.0f;
    }
}

// K3: edge scatter-add (4 edges per thread)
__global__ void k_edge(const int* __restrict__ edge_src,
                       const int* __restrict__ edge_dst, int E)
{
    int i = (blockIdx.x * blockDim.x + threadIdx.x) * 4;
    if (i + 3 < E) {
        int4 s = *(const int4*)(edge_src + i);
        int4 d = *(const int4*)(edge_dst + i);
        atomicAdd(&g_agg[d.x], g_sv[s.x]);
        atomicAdd(&g_agg[d.y], g_sv[s.y]);
        atomicAdd(&g_agg[d.z], g_sv[s.z]);
        atomicAdd(&g_agg[d.w], g_sv[s.w]);
    } else {
        for (int j = i; j < E; j++)
            atomicAdd(&g_agg[edge_dst[j]], g_sv[edge_src[j]]);
    }
}

// K4: per-candidate scores. One warp handles TWO candidates; all 8 global
// float4 loads issued up-front for MLP. Weights held in registers.
__global__ void __launch_bounds__(256)
k_cand(const float* __restrict__ x,
       const float* __restrict__ w_ego_u,
       const float* __restrict__ w_layer_u,
       const float* __restrict__ n_imp,
       const int*   __restrict__ u_ids,
       const int*   __restrict__ batch_ptr, int M)
{
    int t = threadIdx.x;
    int warp = t >> 5, lane = t & 31;
    int m0 = blockIdx.x * 16 + warp * 2;   // 8 warps * 2 candidates
    if (m0 >= M) return;
    int  m1   = m0 + 1;
    bool has1 = (m1 < M);

    int u0 = __ldg(u_ids + m0);
    int b0 = __ldg(batch_ptr + m0);
    int u1 = has1 ? __ldg(u_ids + m1) : u0;
    int b1 = has1 ? __ldg(batch_ptr + m1) : b0;

    const float4* x4 = (const float4*)x;
    const float4* g4 = (const float4*)g_groot;
    int ia = lane, ib = lane + 32;        // float4 indices covering 256 floats

    // ---- all global loads issued back-to-back (MLP = 8) ----
    float4 xa0 = __ldg(x4 + (size_t)u0 * 64 + ia);
    float4 xb0 = __ldg(x4 + (size_t)u0 * 64 + ib);
    float4 xa1 = __ldg(x4 + (size_t)u1 * 64 + ia);
    float4 xb1 = __ldg(x4 + (size_t)u1 * 64 + ib);
    float4 ga0 = __ldg(g4 + (size_t)b0 * 64 + ia);
    float4 gb0 = __ldg(g4 + (size_t)b0 * 64 + ib);
    float4 ga1 = __ldg(g4 + (size_t)b1 * 64 + ia);
    float4 gb1 = __ldg(g4 + (size_t)b1 * 64 + ib);
    float4 wea = __ldg(((const float4*)w_ego_u)   + ia);
    float4 web = __ldg(((const float4*)w_ego_u)   + ib);
    float4 wla = __ldg(((const float4*)w_layer_u) + ia);
    float4 wlb = __ldg(((const float4*)w_layer_u) + ib);

    // ---- six partial reductions ----
    float dot0 = dot4(xa0, ga0) + dot4(xb0, gb0);
    float dot1 = dot4(xa1, ga1) + dot4(xb1, gb1);

    float e0x = xa0.x * wea.x, e0y = xa0.y * wea.y, e0z = xa0.z * wea.z, e0w = xa0.w * wea.w;
    float f0x = xb0.x * web.x, f0y = xb0.y * web.y, f0z = xb0.z * web.z, f0w = xb0.w * web.w;
    float nu20 = e0x*e0x + e0y*e0y + e0z*e0z + e0w*e0w
               + f0x*f0x + f0y*f0y + f0z*f0z + f0w*f0w;
    float e1x = xa1.x * wea.x, e1y = xa1.y * wea.y, e1z = xa1.z * wea.z, e1w = xa1.w * wea.w;
    float f1x = xb1.x * web.x, f1y = xb1.y * web.y, f1z = xb1.z * web.z, f1w = xb1.w * web.w;
    float nu21 = e1x*e1x + e1y*e1y + e1z*e1z + e1w*e1w
               + f1x*f1x + f1y*f1y + f1z*f1z + f1w*f1w;

    float su0 = dot4(xa0, wla) + dot4(xb0, wlb);
    float su1 = dot4(xa1, wla) + dot4(xb1, wlb);

    #pragma unroll
    for (int o = 16; o; o >>= 1) {
        dot0 += __shfl_xor_sync(0xffffffffu, dot0, o);
        dot1 += __shfl_xor_sync(0xffffffffu, dot1, o);
        nu20 += __shfl_xor_sync(0xffffffffu, nu20, o);
        nu21 += __shfl_xor_sync(0xffffffffu, nu21, o);
        su0  += __shfl_xor_sync(0xffffffffu, su0,  o);
        su1  += __shfl_xor_sync(0xffffffffu, su1,  o);
    }

    // ---- warp-uniform finalize (scalar loads broadcast across the warp) ----
    float nr0 = fmaxf(g_nr[b0], 1e-6f), nr1 = fmaxf(g_nr[b1], 1e-6f);
    float bf0 = g_bf[b0],               bf1 = g_bf[b1];
    float ni0 = __ldg(n_imp + u0),      ni1 = __ldg(n_imp + u1);
    float ag0 = g_agg[m0],              ag1 = has1 ? g_agg[m1] : 0.f;

    float ego0 = dot0 / (nr0 * fmaxf(sqrtf(nu20), 1e-6f));
    float ego1 = dot1 / (nr1 * fmaxf(sqrtf(nu21), 1e-6f));
    float p0 = (0.5f * ego0 + 0.5f * tanhf(ag0 + su0)) * ni0 * bf0;
    float p1 = (0.5f * ego1 + 0.5f * tanhf(ag1 + su1)) * ni1 * bf1;

    if (lane == 0) {
        g_pu[m0] = p0;
        unsigned k0 = f2key(p0);
        if (has1) {
            g_pu[m1] = p1;
            unsigned k1 = f2key(p1);
            if (b0 == b1) {
                atomicMax(&g_pnorm[b0], k0 > k1 ? k0 : k1);
            } else {
                atomicMax(&g_pnorm[b0], k0);
                atomicMax(&g_pnorm[b1], k1);
            }
        } else {
            atomicMax(&g_pnorm[b0], k0);
        }
    }
}

// K5: normalize + nan/inf replace + clip (vectorized)
__global__ void k_final(const int* __restrict__ batch_ptr,
                        float* __restrict__ out, int M)
{
    int i = blockIdx.x * blockDim.x + threadIdx.x;
    int m = i * 4;
    if (m + 3 < M) {
        int4   bp = *(const int4*)(batch_ptr + m);
        float4 pu = *(const float4*)(g_pu + m);
        float4 r;
        {
            float p = pu.x / key2f(g_pnorm[bp.x]) + 1.0f;
            if (isnan(p)) p = 0.0f; else if (isinf(p)) p = 1.0f;
            r.x = fminf(fmaxf(p, 1e-5f), 1.0f);
        }
        {
            float p = pu.y / key2f(g_pnorm[bp.y]) + 1.0f;
            if (isnan(p)) p = 0.0f; else if (isinf(p)) p = 1.0f;
            r.y = fminf(fmaxf(p, 1e-5f), 1.0f);
        }
        {
            float p = pu.z / key2f(g_pnorm[bp.z]) + 1.0f;
            if (isnan(p)) p = 0.0f; else if (isinf(p)) p = 1.0f;
            r.z = fminf(fmaxf(p, 1e-5f), 1.0f);
        }
        {
            float p = pu.w / key2f(g_pnorm[bp.w]) + 1.0f;
            if (isnan(p)) p = 0.0f; else if (isinf(p)) p = 1.0f;
            r.w = fminf(fmaxf(p, 1e-5f), 1.0f);
        }
        *(float4*)(out + m) = r;
    } else {
        for (int j = m; j < M; j++) {
            float p = g_pu[j] / key2f(g_pnorm[batch_ptr[j]]) + 1.0f;
            if (isnan(p)) p = 0.0f; else if (isinf(p)) p = 1.0f;
            out[j] = fminf(fmaxf(p, 1e-5f), 1.0f);
        }
    }
}

extern "C" void kernel_launch(void* const* d_in, const int* in_sizes, int n_in,
                              void* d_out, int out_size)
{
    const float* x           = (const float*)d_in[0];
    const float* w_ego_root  = (const float*)d_in[1];
    const float* w_ego_u     = (const float*)d_in[2];
    const float* w_layer_v   = (const float*)d_in[3];
    const float* w_layer_u   = (const float*)d_in[4];
    const float* n_imp       = (const float*)d_in[5];
    const float* budgets     = (const float*)d_in[6];
    const int*   batch_nodes = (const int*)d_in[7];
    const int*   u_ids       = (const int*)d_in[8];
    const int*   batch_ptr   = (const int*)d_in[9];
    const int*   edge_src    = (const int*)d_in[10];
    const int*   edge_dst    = (const int*)d_in[11];
    float* out = (float*)d_out;

    int B = in_sizes[7];
    int M = in_sizes[8];
    int E = in_sizes[10];

    k_root<<<B, FDIM>>>(x, w_ego_root, w_ego_u, w_layer_v, budgets, batch_nodes);
    k_zero<<<(M / 4 + 255) / 256, 256>>>(M);
    k_edge<<<(E / 4 + 255) / 256, 256>>>(edge_src, edge_dst, E);
    k_cand<<<(M + 15) / 16, 256>>>(x, w_ego_u, w_layer_u, n_imp, u_ids, batch_ptr, M);
    k_final<<<(M / 4 + 255) / 256, 256>>>(batch_ptr, out, M);
}